// round 15
// baseline (speedup 1.0000x reference)
#include <cuda_runtime.h>
#include <math.h>

#define BSZ 2048
#define TT 8
#define NQ 10
#define FULLM 0xffffffffu

__device__ const int MASKD[10] = {0x304,0x48,0x2F9,0x86,0x44,0x204,0x16,0xC,0x1,0x25};

__device__ __forceinline__ float fast_tanh(float x) {
    float y; asm("tanh.approx.f32 %0, %1;" : "=f"(y) : "f"(x)); return y;
}
__device__ __forceinline__ float fast_sigmoid(float x) {
    return 0.5f * fast_tanh(0.5f * x) + 0.5f;
}

// One warp per batch element. 2048 blocks x 32 threads.
// sAll word layout (16B-aligned, bank-disjoint bases per access phase):
//  [  0.. 39] input features   (10 x float4 {f0,f1,f2,pad})
//  [ 40.. 79] candidate features
//  [ 80..119] temporal features
//  [120..139] forget folded    (10 x float2)
//  [140..159] memory folded    (10 x float2)
//  [160..171] input pz vector  (10 + pad)
//  [172..183] cand  pz vector  (10 + pad)
__global__ __launch_bounds__(32, 14) void qlstm_kernel(
    const float* __restrict__ x, const float* __restrict__ Wx,
    const float* __restrict__ Wh, const float* __restrict__ bias,
    const float* __restrict__ R, float* __restrict__ out)
{
    __shared__ __align__(16) float sAll[184];

    const int lane = threadIdx.x;
    const int b = blockIdx.x;

    for (int i = lane; i < 184; i += 32) sAll[i] = 0.f;

    // ---- matvec column ownership ----
    int colA = (lane < 30) ? lane : 80;                            // 0..29 | temporal(80)
    int colB;
    if (lane < 20)      colB = 41 + 3 * (lane >> 1) + (lane & 1);  // candidate
    else if (lane < 30) colB = 50 + lane;                          // memory 70..79
    else                colB = 80;

    float wxA[NQ], whA[NQ], wxB[NQ], whB[NQ];
    #pragma unroll
    for (int k = 0; k < NQ; k++) {
        wxA[k] = Wx[k*81 + colA];  whA[k] = Wh[k*81 + colA];
        wxB[k] = Wx[k*81 + colB];  whB[k] = Wh[k*81 + colB];
    }
    const float bA = bias[colA], bB = bias[colB];

    // ---- gate weights in registers ----
    const int n1 = lane % 10;
    float Rp1[20];
    if (lane < 10) {            // forget, folded (f1=f2)
        #pragma unroll
        for (int q = 0; q < NQ; q++) {
            Rp1[2*q]   = R[(3*q)*10 + n1];
            Rp1[2*q+1] = R[(3*q+1)*10 + n1] + R[(3*q+2)*10 + n1];
        }
    } else if (lane < 20) {     // memory, folded (f2=0)
        #pragma unroll
        for (int q = 0; q < NQ; q++) {
            Rp1[2*q]   = R[1200 + (3*q)*10 + n1];
            Rp1[2*q+1] = R[1200 + (3*q+1)*10 + n1];
        }
    } else {
        #pragma unroll
        for (int f = 0; f < 20; f++) Rp1[f] = 0.f;
    }
    float Rp2[30];
    if (lane < 30) {            // input / candidate / temporal
        int g = lane / 10;
        int base = ((g == 0) ? 1 : ((g == 1) ? 3 : 5)) * 300;
        #pragma unroll
        for (int f = 0; f < 30; f++) Rp2[f] = R[base + f*10 + n1];
    } else {
        #pragma unroll
        for (int f = 0; f < 30; f++) Rp2[f] = 0.f;
    }

    // circ_output constant -> og fixed
    float og = 0.f;
    if (lane < NQ) {
        float G2 = 0.f;
        #pragma unroll
        for (int q = 0; q < NQ; q++) G2 += R[600 + (3*q+1)*10 + lane];
        og = fast_sigmoid(G2);
    }

    // ---- precompute bias + x_t @ Wx into registers ----
    float pxA[TT], pxB[TT];
    #pragma unroll
    for (int t = 0; t < TT; t++) {
        float xv = (lane < NQ) ? x[(b*TT + t)*NQ + lane] : 0.f;
        float a0 = bA, a1v = 0.f, c0 = bB, c1v = 0.f;
        #pragma unroll
        for (int k = 0; k < NQ; k += 2) {
            float xk0 = __shfl_sync(FULLM, xv, k);
            float xk1 = __shfl_sync(FULLM, xv, k + 1);
            a0  = fmaf(xk0, wxA[k],   a0);
            a1v = fmaf(xk1, wxA[k+1], a1v);
            c0  = fmaf(xk0, wxB[k],   c0);
            c1v = fmaf(xk1, wxB[k+1], c1v);
        }
        pxA[t] = a0 + a1v;
        pxB[t] = c0 + c1v;
    }

    // ---- per-lane constants ----
    const bool g0 = lane < 10, g1 = (lane >= 10 && lane < 20), g2 = (lane >= 20 && lane < 30);
    const int q1i = lane - 10, q2i = lane - 20;
    const int iA1 = g1 ? 2*lane - 10 : 0;                     // input col 10+2q
    const int iA2 = g1 ? 2*lane - 9  : 0;                     // input col 11+2q
    const int iB1 = g0 ? 20 + lane : (g2 ? 2*lane - 40 : 0);  // mem col / cand col1
    const int iB2 = g2 ? 2*lane - 39 : 0;                     // cand col2
    // masked-product mask: input = exclusive prefix, cand = CZ partners
    unsigned m = 0;
    if (g1) m = (1u << q1i) - 1u;
    else if (g2) m = (unsigned)MASKD[q2i];
    const int pzIdx = g1 ? (160 + q1i) : (g2 ? (172 + q2i) : 160);
    const float4* Zbase = (const float4*)(sAll + (g2 ? 172 : 160));

    const float PIH = 1.57079632679489662f;
    float hv = 0.f, creg = 0.f;

    #pragma unroll
    for (int t = 0; t < TT; t++) {
        // ---- matvec: h @ Wh, 2-way split chains ----
        float pA0 = pxA[t], pA1 = 0.f, pB0 = pxB[t], pB1 = 0.f;
        #pragma unroll
        for (int k = 0; k < NQ; k += 2) {
            float hk0 = __shfl_sync(FULLM, hv, k);
            float hk1 = __shfl_sync(FULLM, hv, k + 1);
            pA0 = fmaf(hk0, whA[k],   pA0);
            pA1 = fmaf(hk1, whA[k+1], pA1);
            pB0 = fmaf(hk0, whB[k],   pB0);
            pB1 = fmaf(hk1, whB[k+1], pB1);
        }
        float pA = pA0 + pA1, pB = pB0 + pB1;

        float a1 = __shfl_sync(FULLM, pA, iA1);
        float a2 = __shfl_sync(FULLM, pA, iA2);
        float b1 = __shfl_sync(FULLM, pB, iB1);
        float b2v = __shfl_sync(FULLM, pB, iB2);
        float tp = __shfl_sync(FULLM, pA, 30);

        // ---- branchless angles: forget/input/cand via alpha, memory via beta ----
        float alpha = g0 ? pA : (g1 ? a1 : b1 - PIH);
        float beta  = g0 ? b1 : (g1 ? a2 : b2v);
        float s1, c1; __sincosf(alpha, &s1, &c1);
        float s2, c2; __sincosf(beta,  &s2, &c2);
        float pz  = -s1;
        float xrF = 0.5f * c1;              // forget xr (beta-independent)
        float xr  = g0 ? xrF : xrF * c2;
        float xi  = 0.5f * c1 * s2;
        float pzM = -s2, xrM = 0.5f * c2;   // memory (valid on g0 lanes)

        // ---- temporal closed form (uniform over warp) ----
        float sA5, cA5;  __sincosf(0.05f * tp, &sA5, &cA5);
        float sA10, cA10; __sincosf(0.1f  * tp, &sA10, &cA10);
        float s2z, c2z;  __sincosf(0.2f  * tp, &s2z, &c2z);
        float pz0 = cA5;
        float xi0 = -0.5f * sA5;
        float P   = sA5 * sA10;
        float xrP = 0.5f * cA10;            // FIX: was 0.5*cA5
        float xiP = 0.5f * sA10 * cA5;
        float EPi = s2z * P;
        float er1 = c2z*c2z - (s2z*pz0)*EPi;
        float ei1 = c2z * s2z * (P + pz0);
        float er2 = c2z*c2z - EPi*EPi;
        float ei2 = 2.f * c2z * EPi;

        // ---- neighbor shuffles (full-warp, group-local meaning) ----
        float pzn  = __shfl_xor_sync(FULLM, pz,  1);   // forget neighbor (g0)
        float pznM = __shfl_xor_sync(FULLM, pzM, 1);   // memory neighbor (g0)
        float xrn  = __shfl_down_sync(FULLM, xr, 1);   // input q+1 (g1)

        // ---- publish pz vectors (input & cand) ----
        if (g1 || g2) sAll[pzIdx] = pz;
        __syncwarp();

        // ---- unified masked product over own circuit's pz vector ----
        float4 za = Zbase[0], zb = Zbase[1], zc = Zbase[2];
        float t0 = (m & 1u)   ? za.x : 1.f;
        float t1v = (m & 2u)  ? za.y : 1.f;
        float t2v = (m & 4u)  ? za.z : 1.f;
        float t3 = (m & 8u)   ? za.w : 1.f;
        float t4 = (m & 16u)  ? zb.x : 1.f;
        float t5 = (m & 32u)  ? zb.y : 1.f;
        float t6 = (m & 64u)  ? zb.z : 1.f;
        float t7 = (m & 128u) ? zb.w : 1.f;
        float t8 = (m & 256u) ? zc.x : 1.f;
        float t9 = (m & 512u) ? zc.y : 1.f;
        float prod = ((t0*t1v)*(t2v*t3)) * ((t4*t5)*(t6*t7)) * (t8*t9);

        // ---- feature assembly + stores ----
        if (g0) {
            ((float2*)(sAll + 120))[lane] = make_float2(pz, 1.41421356237f * xrF * pzn);
            ((float2*)(sAll + 140))[lane] = make_float2(pzM, 2.f * xrM * pznM);
        } else if (g1) {
            // input circuit (prod = exclusive prefix)
            float incl = prod * pz;
            float C = (q1i < 9) ? 2.f * xrn : 1.f;
            ((float4*)(sAll))[q1i] = make_float4(incl, 2.f*C*xr, 2.f*C*xi*prod, 0.f);
            // temporal features (4 cases by q)
            bool mid = (q1i >= 2) && (q1i <= 8);
            float er = (q1i == 1) ? er1 : (mid ? er2 : c2z);
            float ei = (q1i == 1) ? ei1 : (mid ? ei2 : EPi);
            float pzT = (q1i == 0) ? pz0 : P;
            float xrT = (q1i == 0) ? 0.f : xrP;
            float xiT = (q1i == 0) ? xi0 : xiP;
            ((float4*)(sAll + 80))[q1i] = make_float4(
                pzT, 2.f*(xrT*er - xiT*ei), 2.f*(xrT*ei + xiT*er), 0.f);
        } else if (g2) {
            ((float4*)(sAll + 40))[q2i] = make_float4(pz, 2.f*xr*prod, 2.f*xi*prod, 0.f);
        }
        __syncwarp();

        // ---- gates pass1: forget/memory folded (5 x LDS.128) ----
        float3 A1 = make_float3(0.f, 0.f, 0.f);
        {
            const float4* F1 = (const float4*)(sAll + (g0 ? 120 : 140));
            #pragma unroll
            for (int i = 0; i < 5; i++) {
                float4 fv = F1[i];
                A1.x = fmaf(fv.x, Rp1[4*i],   A1.x);
                A1.y = fmaf(fv.y, Rp1[4*i+1], A1.y);
                A1.z = fmaf(fv.z, Rp1[4*i+2], A1.z);
                A1.x = fmaf(fv.w, Rp1[4*i+3], A1.x);
            }
        }
        float gp1 = (A1.x + A1.y) + A1.z;

        // ---- gates pass2: input/cand/temporal (10 x LDS.128, .xyz used) ----
        float3 A2 = make_float3(0.f, 0.f, 0.f);
        {
            int gidx = (lane < 30) ? lane / 10 : 0;
            const float4* F2 = (const float4*)(sAll + 40*gidx);
            #pragma unroll
            for (int i = 0; i < 10; i++) {
                float4 fv = F2[i];
                A2.x = fmaf(fv.x, Rp2[3*i],   A2.x);
                A2.y = fmaf(fv.y, Rp2[3*i+1], A2.y);
                A2.z = fmaf(fv.z, Rp2[3*i+2], A2.z);
            }
        }
        float gp2 = (A2.x + A2.y) + A2.z;

        // ---- gather gates to lanes 0..9, update cell ----
        float mqv = __shfl_sync(FULLM, gp1, lane + 10);
        float ggv = __shfl_sync(FULLM, gp2, lane + 10);
        float tmv = __shfl_sync(FULLM, gp2, lane + 20);
        float hn = 0.f;
        if (lane < NQ) {
            float fg = fast_sigmoid(gp1);
            float ig = fast_sigmoid(gp2);
            float mq = fast_sigmoid(mqv);
            float gg = fast_tanh(ggv);
            float tm = fast_tanh(tmv);
            float cn = (fg * creg + ig * gg) * mq;
            hn = og * fast_tanh(cn) + 0.1f * tm;
            creg = cn;
            out[(b*TT + t)*NQ + lane] = hn;
        }
        hv = hn;
    }
}

extern "C" void kernel_launch(void* const* d_in, const int* in_sizes, int n_in,
                              void* d_out, int out_size)
{
    const float* x    = (const float*)d_in[0];
    const float* Wx   = (const float*)d_in[1];
    const float* Wh   = (const float*)d_in[2];
    const float* bias = (const float*)d_in[3];
    const float* R    = (const float*)d_in[4];
    float* out = (float*)d_out;

    qlstm_kernel<<<BSZ, 32>>>(x, Wx, Wh, bias, R, out);
}

// round 16
// speedup vs baseline: 1.3939x; 1.3939x over previous
#include <cuda_runtime.h>
#include <math.h>

#define BSZ 2048
#define TT 8
#define NQ 10
#define FULLM 0xffffffffu

__device__ const int MASKD[10] = {0x304,0x48,0x2F9,0x86,0x44,0x204,0x16,0xC,0x1,0x25};

__device__ __forceinline__ float fast_tanh(float x) {
    float y; asm("tanh.approx.f32 %0, %1;" : "=f"(y) : "f"(x)); return y;
}
__device__ __forceinline__ float fast_sigmoid(float x) {
    return 0.5f * fast_tanh(0.5f * x) + 0.5f;
}

// One warp per batch element. 2048 blocks x 32 threads.
// sAll word layout (16B-aligned, bank-disjoint bases per access phase):
//  [  0.. 39] input features   (10 x float4 {f0,f1,f2,pad})
//  [ 40.. 79] candidate features
//  [ 80..119] temporal features
//  [120..139] forget folded    (10 x float2)
//  [140..159] memory folded    (10 x float2)
//  [160..171] input pz vector  (10 + pad)
//  [172..183] cand  pz vector  (10 + pad)
__global__ __launch_bounds__(32, 14) void qlstm_kernel(
    const float* __restrict__ x, const float* __restrict__ Wx,
    const float* __restrict__ Wh, const float* __restrict__ bias,
    const float* __restrict__ R, float* __restrict__ out)
{
    __shared__ __align__(16) float sAll[184];
    __shared__ float sPxA[TT][32], sPxB[TT][32];   // bias + x_t @ Wx per lane-column

    const int lane = threadIdx.x;
    const int b = blockIdx.x;

    for (int i = lane; i < 184; i += 32) sAll[i] = 0.f;

    // ---- matvec column ownership ----
    int colA = (lane < 30) ? lane : 80;                            // 0..29 | temporal(80)
    int colB;
    if (lane < 20)      colB = 41 + 3 * (lane >> 1) + (lane & 1);  // candidate
    else if (lane < 30) colB = 50 + lane;                          // memory 70..79
    else                colB = 80;

    float wxA[NQ], whA[NQ], wxB[NQ], whB[NQ];
    #pragma unroll
    for (int k = 0; k < NQ; k++) {
        wxA[k] = Wx[k*81 + colA];  whA[k] = Wh[k*81 + colA];
        wxB[k] = Wx[k*81 + colB];  whB[k] = Wh[k*81 + colB];
    }
    const float bA = bias[colA], bB = bias[colB];

    // ---- gate weights in registers ----
    const int n1 = lane % 10;
    float Rp1[20];
    if (lane < 10) {            // forget, folded (f1=f2)
        #pragma unroll
        for (int q = 0; q < NQ; q++) {
            Rp1[2*q]   = R[(3*q)*10 + n1];
            Rp1[2*q+1] = R[(3*q+1)*10 + n1] + R[(3*q+2)*10 + n1];
        }
    } else if (lane < 20) {     // memory, folded (f2=0)
        #pragma unroll
        for (int q = 0; q < NQ; q++) {
            Rp1[2*q]   = R[1200 + (3*q)*10 + n1];
            Rp1[2*q+1] = R[1200 + (3*q+1)*10 + n1];
        }
    } else {
        #pragma unroll
        for (int f = 0; f < 20; f++) Rp1[f] = 0.f;
    }
    float Rp2[30];
    if (lane < 30) {            // input / candidate / temporal
        int g = lane / 10;
        int base = ((g == 0) ? 1 : ((g == 1) ? 3 : 5)) * 300;
        #pragma unroll
        for (int f = 0; f < 30; f++) Rp2[f] = R[base + f*10 + n1];
    } else {
        #pragma unroll
        for (int f = 0; f < 30; f++) Rp2[f] = 0.f;
    }

    // circ_output constant -> og fixed
    float og = 0.f;
    if (lane < NQ) {
        float G2 = 0.f;
        #pragma unroll
        for (int q = 0; q < NQ; q++) G2 += R[600 + (3*q+1)*10 + lane];
        og = fast_sigmoid(G2);
    }

    // ---- precompute bias + x_t @ Wx into shared (rolled: small code) ----
    #pragma unroll 1
    for (int t = 0; t < TT; t++) {
        float xv = (lane < NQ) ? x[(b*TT + t)*NQ + lane] : 0.f;
        float a0 = bA, a1v = 0.f, c0 = bB, c1v = 0.f;
        #pragma unroll
        for (int k = 0; k < NQ; k += 2) {
            float xk0 = __shfl_sync(FULLM, xv, k);
            float xk1 = __shfl_sync(FULLM, xv, k + 1);
            a0  = fmaf(xk0, wxA[k],   a0);
            a1v = fmaf(xk1, wxA[k+1], a1v);
            c0  = fmaf(xk0, wxB[k],   c0);
            c1v = fmaf(xk1, wxB[k+1], c1v);
        }
        sPxA[t][lane] = a0 + a1v;
        sPxB[t][lane] = c0 + c1v;
    }

    // ---- per-lane constants ----
    const bool g0 = lane < 10, g1 = (lane >= 10 && lane < 20), g2 = (lane >= 20 && lane < 30);
    const int q1i = lane - 10, q2i = lane - 20;
    const int iA1 = g1 ? 2*lane - 10 : 0;                     // input col 10+2q
    const int iA2 = g1 ? 2*lane - 9  : 0;                     // input col 11+2q
    const int iB1 = g0 ? 20 + lane : (g2 ? 2*lane - 40 : 0);  // mem col / cand col1
    const int iB2 = g2 ? 2*lane - 39 : 0;                     // cand col2
    // masked-product mask: input = exclusive prefix, cand = CZ partners
    unsigned m = 0;
    if (g1) m = (1u << q1i) - 1u;
    else if (g2) m = (unsigned)MASKD[q2i];
    const int pzIdx = g1 ? (160 + q1i) : (g2 ? (172 + q2i) : 160);
    const float4* Zbase = (const float4*)(sAll + (g2 ? 172 : 160));

    const float PIH = 1.57079632679489662f;
    float hv = 0.f, creg = 0.f;

    __syncwarp();

    #pragma unroll 1
    for (int t = 0; t < TT; t++) {
        // ---- matvec: h @ Wh, 2-way split chains (px from shared, independent) ----
        float pA0 = sPxA[t][lane], pA1 = 0.f, pB0 = sPxB[t][lane], pB1 = 0.f;
        #pragma unroll
        for (int k = 0; k < NQ; k += 2) {
            float hk0 = __shfl_sync(FULLM, hv, k);
            float hk1 = __shfl_sync(FULLM, hv, k + 1);
            pA0 = fmaf(hk0, whA[k],   pA0);
            pA1 = fmaf(hk1, whA[k+1], pA1);
            pB0 = fmaf(hk0, whB[k],   pB0);
            pB1 = fmaf(hk1, whB[k+1], pB1);
        }
        float pA = pA0 + pA1, pB = pB0 + pB1;

        float a1 = __shfl_sync(FULLM, pA, iA1);
        float a2 = __shfl_sync(FULLM, pA, iA2);
        float b1 = __shfl_sync(FULLM, pB, iB1);
        float b2v = __shfl_sync(FULLM, pB, iB2);
        float tp = __shfl_sync(FULLM, pA, 30);

        // ---- branchless angles: forget/input/cand via alpha, memory via beta ----
        float alpha = g0 ? pA : (g1 ? a1 : b1 - PIH);
        float beta  = g0 ? b1 : (g1 ? a2 : b2v);
        float s1, c1; __sincosf(alpha, &s1, &c1);
        float s2, c2; __sincosf(beta,  &s2, &c2);
        float pz  = -s1;
        float xrF = 0.5f * c1;              // forget xr (beta-independent)
        float xr  = g0 ? xrF : xrF * c2;
        float xi  = 0.5f * c1 * s2;
        float pzM = -s2, xrM = 0.5f * c2;   // memory (valid on g0 lanes)

        // ---- temporal closed form (uniform over warp) ----
        float sA5, cA5;  __sincosf(0.05f * tp, &sA5, &cA5);
        float sA10, cA10; __sincosf(0.1f  * tp, &sA10, &cA10);
        float s2z, c2z;  __sincosf(0.2f  * tp, &s2z, &c2z);
        float pz0 = cA5;
        float xi0 = -0.5f * sA5;
        float P   = sA5 * sA10;
        float xrP = 0.5f * cA10;
        float xiP = 0.5f * sA10 * cA5;
        float EPi = s2z * P;
        float er1 = c2z*c2z - (s2z*pz0)*EPi;
        float ei1 = c2z * s2z * (P + pz0);
        float er2 = c2z*c2z - EPi*EPi;
        float ei2 = 2.f * c2z * EPi;

        // ---- neighbor shuffles (full-warp, group-local meaning) ----
        float pzn  = __shfl_xor_sync(FULLM, pz,  1);   // forget neighbor (g0)
        float pznM = __shfl_xor_sync(FULLM, pzM, 1);   // memory neighbor (g0)
        float xrn  = __shfl_down_sync(FULLM, xr, 1);   // input q+1 (g1)

        // ---- publish pz vectors (input & cand) ----
        if (g1 || g2) sAll[pzIdx] = pz;
        __syncwarp();

        // ---- unified masked product over own circuit's pz vector ----
        float4 za = Zbase[0], zb = Zbase[1], zc = Zbase[2];
        float t0 = (m & 1u)   ? za.x : 1.f;
        float t1v = (m & 2u)  ? za.y : 1.f;
        float t2v = (m & 4u)  ? za.z : 1.f;
        float t3 = (m & 8u)   ? za.w : 1.f;
        float t4 = (m & 16u)  ? zb.x : 1.f;
        float t5 = (m & 32u)  ? zb.y : 1.f;
        float t6 = (m & 64u)  ? zb.z : 1.f;
        float t7 = (m & 128u) ? zb.w : 1.f;
        float t8 = (m & 256u) ? zc.x : 1.f;
        float t9 = (m & 512u) ? zc.y : 1.f;
        float prod = ((t0*t1v)*(t2v*t3)) * ((t4*t5)*(t6*t7)) * (t8*t9);

        // ---- feature assembly + stores ----
        if (g0) {
            ((float2*)(sAll + 120))[lane] = make_float2(pz, 1.41421356237f * xrF * pzn);
            ((float2*)(sAll + 140))[lane] = make_float2(pzM, 2.f * xrM * pznM);
        } else if (g1) {
            // input circuit (prod = exclusive prefix)
            float incl = prod * pz;
            float C = (q1i < 9) ? 2.f * xrn : 1.f;
            ((float4*)(sAll))[q1i] = make_float4(incl, 2.f*C*xr, 2.f*C*xi*prod, 0.f);
            // temporal features (4 cases by q)
            bool mid = (q1i >= 2) && (q1i <= 8);
            float er = (q1i == 1) ? er1 : (mid ? er2 : c2z);
            float ei = (q1i == 1) ? ei1 : (mid ? ei2 : EPi);
            float pzT = (q1i == 0) ? pz0 : P;
            float xrT = (q1i == 0) ? 0.f : xrP;
            float xiT = (q1i == 0) ? xi0 : xiP;
            ((float4*)(sAll + 80))[q1i] = make_float4(
                pzT, 2.f*(xrT*er - xiT*ei), 2.f*(xrT*ei + xiT*er), 0.f);
        } else if (g2) {
            ((float4*)(sAll + 40))[q2i] = make_float4(pz, 2.f*xr*prod, 2.f*xi*prod, 0.f);
        }
        __syncwarp();

        // ---- gates pass1: forget/memory folded (5 x LDS.128) ----
        float3 A1 = make_float3(0.f, 0.f, 0.f);
        {
            const float4* F1 = (const float4*)(sAll + (g0 ? 120 : 140));
            #pragma unroll
            for (int i = 0; i < 5; i++) {
                float4 fv = F1[i];
                A1.x = fmaf(fv.x, Rp1[4*i],   A1.x);
                A1.y = fmaf(fv.y, Rp1[4*i+1], A1.y);
                A1.z = fmaf(fv.z, Rp1[4*i+2], A1.z);
                A1.x = fmaf(fv.w, Rp1[4*i+3], A1.x);
            }
        }
        float gp1 = (A1.x + A1.y) + A1.z;

        // ---- gates pass2: input/cand/temporal (10 x LDS.128, .xyz used) ----
        float3 A2 = make_float3(0.f, 0.f, 0.f);
        {
            int gidx = (lane < 30) ? lane / 10 : 0;
            const float4* F2 = (const float4*)(sAll + 40*gidx);
            #pragma unroll
            for (int i = 0; i < 10; i++) {
                float4 fv = F2[i];
                A2.x = fmaf(fv.x, Rp2[3*i],   A2.x);
                A2.y = fmaf(fv.y, Rp2[3*i+1], A2.y);
                A2.z = fmaf(fv.z, Rp2[3*i+2], A2.z);
            }
        }
        float gp2 = (A2.x + A2.y) + A2.z;

        // ---- gather gates to lanes 0..9, update cell ----
        float mqv = __shfl_sync(FULLM, gp1, lane + 10);
        float ggv = __shfl_sync(FULLM, gp2, lane + 10);
        float tmv = __shfl_sync(FULLM, gp2, lane + 20);
        float hn = 0.f;
        if (lane < NQ) {
            float fg = fast_sigmoid(gp1);
            float ig = fast_sigmoid(gp2);
            float mq = fast_sigmoid(mqv);
            float gg = fast_tanh(ggv);
            float tm = fast_tanh(tmv);
            float cn = (fg * creg + ig * gg) * mq;
            hn = og * fast_tanh(cn) + 0.1f * tm;
            creg = cn;
            out[(b*TT + t)*NQ + lane] = hn;
        }
        hv = hn;
    }
}

extern "C" void kernel_launch(void* const* d_in, const int* in_sizes, int n_in,
                              void* d_out, int out_size)
{
    const float* x    = (const float*)d_in[0];
    const float* Wx   = (const float*)d_in[1];
    const float* Wh   = (const float*)d_in[2];
    const float* bias = (const float*)d_in[3];
    const float* R    = (const float*)d_in[4];
    float* out = (float*)d_out;

    qlstm_kernel<<<BSZ, 32>>>(x, Wx, Wh, bias, R, out);
}

// round 17
// speedup vs baseline: 1.4904x; 1.0692x over previous
#include <cuda_runtime.h>
#include <math.h>

#define BSZ 2048
#define TT 8
#define NQ 10
#define FULLM 0xffffffffu

__device__ const int MASKD[10] = {0x304,0x48,0x2F9,0x86,0x44,0x204,0x16,0xC,0x1,0x25};

__device__ __forceinline__ float fast_tanh(float x) {
    float y; asm("tanh.approx.f32 %0, %1;" : "=f"(y) : "f"(x)); return y;
}
__device__ __forceinline__ float fast_sigmoid(float x) {
    return 0.5f * fast_tanh(0.5f * x) + 0.5f;
}

// One warp per batch element. 2048 blocks x 32 threads.
// Column ownership is chosen so each lane's stage-2 reads ITS OWN matvec outputs:
//   g0 (0-9):   colA = forget q      colB = memory 70+q
//   g1 (10-19): colA = input 10+2q   colB = input 11+2q
//   g2 (20-29): colA = cand 41+3q    colB = cand 42+3q
//   lane 30:    colA = temporal 80
// sAll word layout (16B-aligned, bank-disjoint bases per access phase):
//  [  0.. 39] input features   (10 x float4 {f0,f1,f2,pad})
//  [ 40.. 79] candidate features
//  [ 80..119] temporal features
//  [120..139] forget folded    (10 x float2)
//  [140..159] memory folded    (10 x float2)
//  [160..171] input pz vector  (10 + pad)
//  [172..183] cand  pz vector  (10 + pad)
__global__ __launch_bounds__(32, 14) void qlstm_kernel(
    const float* __restrict__ x, const float* __restrict__ Wx,
    const float* __restrict__ Wh, const float* __restrict__ bias,
    const float* __restrict__ R, float* __restrict__ out)
{
    __shared__ __align__(16) float sAll[184];
    __shared__ float sPxA[TT][32], sPxB[TT][32];   // bias + x_t @ Wx per lane-column

    const int lane = threadIdx.x;
    const int b = blockIdx.x;

    for (int i = lane; i < 184; i += 32) sAll[i] = 0.f;

    const bool g0 = lane < 10, g1 = (lane >= 10 && lane < 20), g2 = (lane >= 20 && lane < 30);
    const int q1i = lane - 10, q2i = lane - 20;

    // ---- matvec column ownership (consumer-aligned) ----
    int colA, colB;
    if (g0)      { colA = lane;          colB = 70 + lane; }
    else if (g1) { colA = 10 + 2*q1i;    colB = 11 + 2*q1i; }
    else if (g2) { colA = 41 + 3*q2i;    colB = 42 + 3*q2i; }
    else         { colA = 80;            colB = 80; }

    float wxA[NQ], whA[NQ], wxB[NQ], whB[NQ];
    #pragma unroll
    for (int k = 0; k < NQ; k++) {
        wxA[k] = Wx[k*81 + colA];  whA[k] = Wh[k*81 + colA];
        wxB[k] = Wx[k*81 + colB];  whB[k] = Wh[k*81 + colB];
    }
    const float bA = bias[colA], bB = bias[colB];

    // ---- gate weights in registers ----
    const int n1 = lane % 10;
    float Rp1[20];
    if (g0) {                   // forget, folded (f1=f2)
        #pragma unroll
        for (int q = 0; q < NQ; q++) {
            Rp1[2*q]   = R[(3*q)*10 + n1];
            Rp1[2*q+1] = R[(3*q+1)*10 + n1] + R[(3*q+2)*10 + n1];
        }
    } else if (g1) {            // memory, folded (f2=0)
        #pragma unroll
        for (int q = 0; q < NQ; q++) {
            Rp1[2*q]   = R[1200 + (3*q)*10 + n1];
            Rp1[2*q+1] = R[1200 + (3*q+1)*10 + n1];
        }
    } else {
        #pragma unroll
        for (int f = 0; f < 20; f++) Rp1[f] = 0.f;
    }
    float Rp2[30];
    if (lane < 30) {            // input / candidate / temporal
        int g = lane / 10;
        int base = ((g == 0) ? 1 : ((g == 1) ? 3 : 5)) * 300;
        #pragma unroll
        for (int f = 0; f < 30; f++) Rp2[f] = R[base + f*10 + n1];
    } else {
        #pragma unroll
        for (int f = 0; f < 30; f++) Rp2[f] = 0.f;
    }

    // circ_output constant -> og fixed
    float og = 0.f;
    if (lane < NQ) {
        float G2 = 0.f;
        #pragma unroll
        for (int q = 0; q < NQ; q++) G2 += R[600 + (3*q+1)*10 + lane];
        og = fast_sigmoid(G2);
    }

    // ---- precompute bias + x_t @ Wx into shared (rolled; small code) ----
    #pragma unroll 1
    for (int t = 0; t < TT; t++) {
        float xv = (lane < NQ) ? x[(b*TT + t)*NQ + lane] : 0.f;
        float a0 = bA, a1v = 0.f, c0 = bB, c1v = 0.f;
        #pragma unroll
        for (int k = 0; k < NQ; k += 2) {
            float xk0 = __shfl_sync(FULLM, xv, k);
            float xk1 = __shfl_sync(FULLM, xv, k + 1);
            a0  = fmaf(xk0, wxA[k],   a0);
            a1v = fmaf(xk1, wxA[k+1], a1v);
            c0  = fmaf(xk0, wxB[k],   c0);
            c1v = fmaf(xk1, wxB[k+1], c1v);
        }
        sPxA[t][lane] = a0 + a1v;
        sPxB[t][lane] = c0 + c1v;
    }

    // ---- per-lane constants for the masked product ----
    unsigned m = 0;
    if (g1) m = (1u << q1i) - 1u;          // exclusive prefix mask
    else if (g2) m = (unsigned)MASKD[q2i]; // CAND_CZ partner mask
    const int pzIdx = g1 ? (160 + q1i) : (g2 ? (172 + q2i) : 160);
    const float4* Zbase = (const float4*)(sAll + (g2 ? 172 : 160));

    const float PIH = 1.57079632679489662f;
    float hv = 0.f, creg = 0.f;

    __syncwarp();

    #pragma unroll 2
    for (int t = 0; t < TT; t++) {
        // ---- matvec: h @ Wh, 2-way split chains (px from shared, independent) ----
        float pA0 = sPxA[t][lane], pA1 = 0.f, pB0 = sPxB[t][lane], pB1 = 0.f;
        #pragma unroll
        for (int k = 0; k < NQ; k += 2) {
            float hk0 = __shfl_sync(FULLM, hv, k);
            float hk1 = __shfl_sync(FULLM, hv, k + 1);
            pA0 = fmaf(hk0, whA[k],   pA0);
            pA1 = fmaf(hk1, whA[k+1], pA1);
            pB0 = fmaf(hk0, whB[k],   pB0);
            pB1 = fmaf(hk1, whB[k+1], pB1);
        }
        float pA = pA0 + pA1, pB = pB0 + pB1;
        float tp = __shfl_sync(FULLM, pA, 30);

        // ---- angles directly from own columns (no redistribution) ----
        float alpha = g2 ? pA - PIH : pA;
        float s1, c1; __sincosf(alpha, &s1, &c1);
        float s2, c2; __sincosf(pB,    &s2, &c2);
        float pz  = -s1;
        float xrF = 0.5f * c1;              // forget xr (beta-independent)
        float xr  = g0 ? xrF : xrF * c2;
        float xi  = 0.5f * c1 * s2;
        float pzM = -s2, xrM = 0.5f * c2;   // memory (valid on g0 lanes)

        // ---- temporal closed form, double-angle (1 sincos) ----
        float sA5, cA5;  __sincosf(0.05f * tp, &sA5, &cA5);
        float s10 = 2.f * sA5 * cA5;
        float c10 = 1.f - 2.f * sA5 * sA5;
        float s2z = 2.f * s10 * c10;
        float c2z = 1.f - 2.f * s10 * s10;
        float pz0 = cA5;
        float xi0 = -0.5f * sA5;
        float P   = sA5 * s10;
        float xrP = 0.5f * c10;
        float xiP = 0.5f * s10 * cA5;
        float EPi = s2z * P;
        float er1 = c2z*c2z - (s2z*pz0)*EPi;
        float ei1 = c2z * s2z * (P + pz0);
        float er2 = c2z*c2z - EPi*EPi;
        float ei2 = 2.f * c2z * EPi;

        // ---- neighbor shuffles (group-local meaning) ----
        float pzn  = __shfl_xor_sync(FULLM, pz,  1);   // forget neighbor (g0)
        float pznM = __shfl_xor_sync(FULLM, pzM, 1);   // memory neighbor (g0)
        float xrn  = __shfl_down_sync(FULLM, xr, 1);   // input q+1 (g1)

        // ---- publish pz vectors (input & cand) ----
        if (g1 || g2) sAll[pzIdx] = pz;
        __syncwarp();

        // ---- unified masked product over own circuit's pz vector ----
        float4 za = Zbase[0], zb = Zbase[1], zc = Zbase[2];
        float t0 = (m & 1u)   ? za.x : 1.f;
        float t1v = (m & 2u)  ? za.y : 1.f;
        float t2v = (m & 4u)  ? za.z : 1.f;
        float t3 = (m & 8u)   ? za.w : 1.f;
        float t4 = (m & 16u)  ? zb.x : 1.f;
        float t5 = (m & 32u)  ? zb.y : 1.f;
        float t6 = (m & 64u)  ? zb.z : 1.f;
        float t7 = (m & 128u) ? zb.w : 1.f;
        float t8 = (m & 256u) ? zc.x : 1.f;
        float t9 = (m & 512u) ? zc.y : 1.f;
        float prod = ((t0*t1v)*(t2v*t3)) * ((t4*t5)*(t6*t7)) * (t8*t9);

        // ---- feature assembly + stores ----
        if (g0) {
            ((float2*)(sAll + 120))[lane] = make_float2(pz, 1.41421356237f * xrF * pzn);
            ((float2*)(sAll + 140))[lane] = make_float2(pzM, 2.f * xrM * pznM);
        } else if (g1) {
            // input circuit (prod = exclusive prefix)
            float incl = prod * pz;
            float C = (q1i < 9) ? 2.f * xrn : 1.f;
            ((float4*)(sAll))[q1i] = make_float4(incl, 2.f*C*xr, 2.f*C*xi*prod, 0.f);
            // temporal features (4 cases by q)
            bool mid = (q1i >= 2) && (q1i <= 8);
            float er = (q1i == 1) ? er1 : (mid ? er2 : c2z);
            float ei = (q1i == 1) ? ei1 : (mid ? ei2 : EPi);
            float pzT = (q1i == 0) ? pz0 : P;
            float xrT = (q1i == 0) ? 0.f : xrP;
            float xiT = (q1i == 0) ? xi0 : xiP;
            ((float4*)(sAll + 80))[q1i] = make_float4(
                pzT, 2.f*(xrT*er - xiT*ei), 2.f*(xrT*ei + xiT*er), 0.f);
        } else if (g2) {
            ((float4*)(sAll + 40))[q2i] = make_float4(pz, 2.f*xr*prod, 2.f*xi*prod, 0.f);
        }
        __syncwarp();

        // ---- gates pass1: forget/memory folded (5 x LDS.128) ----
        float3 A1 = make_float3(0.f, 0.f, 0.f);
        {
            const float4* F1 = (const float4*)(sAll + (g0 ? 120 : 140));
            #pragma unroll
            for (int i = 0; i < 5; i++) {
                float4 fv = F1[i];
                A1.x = fmaf(fv.x, Rp1[4*i],   A1.x);
                A1.y = fmaf(fv.y, Rp1[4*i+1], A1.y);
                A1.z = fmaf(fv.z, Rp1[4*i+2], A1.z);
                A1.x = fmaf(fv.w, Rp1[4*i+3], A1.x);
            }
        }
        float gp1 = (A1.x + A1.y) + A1.z;

        // ---- gates pass2: input/cand/temporal (10 x LDS.128, .xyz used) ----
        float3 A2 = make_float3(0.f, 0.f, 0.f);
        {
            int gidx = (lane < 30) ? lane / 10 : 0;
            const float4* F2 = (const float4*)(sAll + 40*gidx);
            #pragma unroll
            for (int i = 0; i < 10; i++) {
                float4 fv = F2[i];
                A2.x = fmaf(fv.x, Rp2[3*i],   A2.x);
                A2.y = fmaf(fv.y, Rp2[3*i+1], A2.y);
                A2.z = fmaf(fv.z, Rp2[3*i+2], A2.z);
            }
        }
        float gp2 = (A2.x + A2.y) + A2.z;

        // ---- gather gates to lanes 0..9, update cell ----
        float mqv = __shfl_sync(FULLM, gp1, lane + 10);
        float ggv = __shfl_sync(FULLM, gp2, lane + 10);
        float tmv = __shfl_sync(FULLM, gp2, lane + 20);
        float hn = 0.f;
        if (lane < NQ) {
            float fg = fast_sigmoid(gp1);
            float ig = fast_sigmoid(gp2);
            float mq = fast_sigmoid(mqv);
            float gg = fast_tanh(ggv);
            float tm = fast_tanh(tmv);
            float cn = (fg * creg + ig * gg) * mq;
            hn = og * fast_tanh(cn) + 0.1f * tm;
            creg = cn;
            out[(b*TT + t)*NQ + lane] = hn;
        }
        hv = hn;
    }
}

extern "C" void kernel_launch(void* const* d_in, const int* in_sizes, int n_in,
                              void* d_out, int out_size)
{
    const float* x    = (const float*)d_in[0];
    const float* Wx   = (const float*)d_in[1];
    const float* Wh   = (const float*)d_in[2];
    const float* bias = (const float*)d_in[3];
    const float* R    = (const float*)d_in[4];
    float* out = (float*)d_out;

    qlstm_kernel<<<BSZ, 32>>>(x, Wx, Wh, bias, R, out);
}